// round 1
// baseline (speedup 1.0000x reference)
#include <cuda_runtime.h>
#include <cstdint>

// ---------------------------------------------------------------------------
// QuantLinear: out[8192, 11008] = x[8192, 4096] @ dequant(W)[4096, 11008] + bias
//   W[k, n] = (w4[k, n] - z4[k/128, n]) * scales[k/128, n]
//   qweight packs 8 consecutive k per int32 (k-major nibbles)
//   qzeros  packs 8 consecutive n per int32 (n-major nibbles)
//
// Strategy: tf32 mma.sync (m16n8k8) GEMM, dequant-on-the-fly into SMEM.
// 128x128x32 CTA tile, 8 warps, double-buffered SMEM, register-staged prefetch.
// ---------------------------------------------------------------------------

namespace {
constexpr int kInF  = 4096;
constexpr int kOutF = 11008;
constexpr int kM    = 8192;          // 4 * 2048

constexpr int BM = 128;
constexpr int BN = 128;
constexpr int BK = 32;
constexpr int NT = kInF / BK;        // 128 k-tiles

constexpr int ASTR = 36;             // A smem row stride (floats): conflict-free frag loads
constexpr int BSTR = 132;            // B smem row stride (floats): conflict-free frag loads
constexpr int AE = BM * ASTR;        // 4608 floats
constexpr int BE = BK * BSTR;        // 4224 floats
constexpr int SMEM_BYTES = (int)(sizeof(float) * 2 * (AE + BE));  // 70656 B
}  // namespace

__device__ __forceinline__ float cvt_tf32(float f) {
    unsigned u;
    asm("cvt.rna.tf32.f32 %0, %1;" : "=r"(u) : "f"(f));
    return __uint_as_float(u);
}

#define MMA_TF32(d, a, b)                                                     \
    asm volatile(                                                             \
        "mma.sync.aligned.m16n8k8.row.col.f32.tf32.tf32.f32 "                 \
        "{%0,%1,%2,%3}, {%4,%5,%6,%7}, {%8,%9}, {%0,%1,%2,%3};"               \
        : "+f"((d)[0]), "+f"((d)[1]), "+f"((d)[2]), "+f"((d)[3])              \
        : "r"((a)[0]), "r"((a)[1]), "r"((a)[2]), "r"((a)[3]),                 \
          "r"((b)[0]), "r"((b)[1]))

__global__ void __launch_bounds__(256, 2)
qlinear_tf32_kernel(const float* __restrict__ x,
                    const float* __restrict__ scales,
                    const float* __restrict__ bias,
                    const int*   __restrict__ qweight,
                    const int*   __restrict__ qzeros,
                    float*       __restrict__ out)
{
    extern __shared__ float smem[];
    float* sAbuf[2] = { smem, smem + AE };
    float* sBbuf[2] = { smem + 2 * AE, smem + 2 * AE + BE };

    const int tid  = threadIdx.x;
    const int lane = tid & 31;
    const int wid  = tid >> 5;
    const int warp_m = (wid & 3) * 32;   // 4 warps along M, 32 rows each
    const int warp_n = (wid >> 2) * 64;  // 2 warps along N, 64 cols each
    const int qrow = lane >> 2;          // groupID (0..7)
    const int qcol = lane & 3;           // threadID_in_group (0..3)

    const int m0 = blockIdx.y * BM;
    const int n0 = blockIdx.x * BN;

    // ---- global-load index precompute -------------------------------------
    // A tile: 128x32 fp32 = 1024 float4; 4 per thread, rows a_r + 32*i, col a_c
    const int a_r = tid >> 3;            // base row 0..31
    const int a_c = (tid & 7) * 4;       // col 0..28
    // B tile: 4 int32-rows x 128 n = 512 int32; 2 per thread, packrow b_pr+2*i
    const int b_pr = tid >> 7;           // 0..1
    const int b_n  = tid & 127;          // 0..127
    const int gn   = n0 + b_n;           // global n
    const int zshift = (b_n & 7) * 4;
    const int zcol   = gn >> 3;

    // ---- register staging --------------------------------------------------
    float4 aS[4];
    int    qwS[2];
    float  scS;
    int    zS;

    const float* xA = x + (long)(m0 + a_r) * kInF + a_c;

    // prologue: tile 0
    {
        const int k0 = 0;
#pragma unroll
        for (int i = 0; i < 4; ++i)
            aS[i] = *reinterpret_cast<const float4*>(xA + (long)i * 32 * kInF + k0);
        const int g = 0;
#pragma unroll
        for (int i = 0; i < 2; ++i)
            qwS[i] = qweight[(long)(b_pr + 2 * i) * kOutF + gn];
        scS = scales[(long)g * kOutF + gn];
        zS  = (qzeros[(long)g * (kOutF / 8) + zcol] >> zshift) & 15;
    }

    // store tile 0 into buffer 0
    {
        float* dA = sAbuf[0];
        float* dB = sBbuf[0];
#pragma unroll
        for (int i = 0; i < 4; ++i) {
            float* p = dA + (a_r + 32 * i) * ASTR + a_c;
            p[0] = cvt_tf32(aS[i].x); p[1] = cvt_tf32(aS[i].y);
            p[2] = cvt_tf32(aS[i].z); p[3] = cvt_tf32(aS[i].w);
        }
#pragma unroll
        for (int i = 0; i < 2; ++i) {
            const int krow = (b_pr + 2 * i) * 8;
#pragma unroll
            for (int j = 0; j < 8; ++j) {
                const int w = (qwS[i] >> (4 * j)) & 15;
                dB[(krow + j) * BSTR + b_n] =
                    cvt_tf32(__int2float_rn(w - zS) * scS);
            }
        }
    }
    __syncthreads();

    float acc[2][8][4];
#pragma unroll
    for (int mt = 0; mt < 2; ++mt)
#pragma unroll
        for (int nt = 0; nt < 8; ++nt)
#pragma unroll
            for (int r = 0; r < 4; ++r) acc[mt][nt][r] = 0.f;

    for (int t = 0; t < NT; ++t) {
        const bool has_next = (t + 1 < NT);

        // issue next tile's global loads early (latency hidden by compute)
        if (has_next) {
            const int k0 = (t + 1) * BK;
#pragma unroll
            for (int i = 0; i < 4; ++i)
                aS[i] = *reinterpret_cast<const float4*>(xA + (long)i * 32 * kInF + k0);
            const int g = k0 >> 7;
            const int qr0 = (k0 >> 3) + b_pr;
#pragma unroll
            for (int i = 0; i < 2; ++i)
                qwS[i] = qweight[(long)(qr0 + 2 * i) * kOutF + gn];
            scS = scales[(long)g * kOutF + gn];
            zS  = (qzeros[(long)g * (kOutF / 8) + zcol] >> zshift) & 15;
        }

        // compute on current buffer
        {
            const float* cA = sAbuf[t & 1];
            const float* cB = sBbuf[t & 1];
#pragma unroll
            for (int ks = 0; ks < 4; ++ks) {
                unsigned af[2][4];
#pragma unroll
                for (int mt = 0; mt < 2; ++mt) {
                    const float* pa = cA + (warp_m + mt * 16 + qrow) * ASTR + ks * 8 + qcol;
                    af[mt][0] = __float_as_uint(pa[0]);
                    af[mt][1] = __float_as_uint(pa[8 * ASTR]);
                    af[mt][2] = __float_as_uint(pa[4]);
                    af[mt][3] = __float_as_uint(pa[8 * ASTR + 4]);
                }
                unsigned bf[8][2];
#pragma unroll
                for (int nt = 0; nt < 8; ++nt) {
                    const float* pb = cB + (ks * 8 + qcol) * BSTR + warp_n + nt * 8 + qrow;
                    bf[nt][0] = __float_as_uint(pb[0]);
                    bf[nt][1] = __float_as_uint(pb[4 * BSTR]);
                }
#pragma unroll
                for (int mt = 0; mt < 2; ++mt)
#pragma unroll
                    for (int nt = 0; nt < 8; ++nt)
                        MMA_TF32(acc[mt][nt], af[mt], bf[nt]);
            }
        }

        // stage -> other buffer
        if (has_next) {
            float* dA = sAbuf[(t + 1) & 1];
            float* dB = sBbuf[(t + 1) & 1];
#pragma unroll
            for (int i = 0; i < 4; ++i) {
                float* p = dA + (a_r + 32 * i) * ASTR + a_c;
                p[0] = cvt_tf32(aS[i].x); p[1] = cvt_tf32(aS[i].y);
                p[2] = cvt_tf32(aS[i].z); p[3] = cvt_tf32(aS[i].w);
            }
#pragma unroll
            for (int i = 0; i < 2; ++i) {
                const int krow = (b_pr + 2 * i) * 8;
#pragma unroll
                for (int j = 0; j < 8; ++j) {
                    const int w = (qwS[i] >> (4 * j)) & 15;
                    dB[(krow + j) * BSTR + b_n] =
                        cvt_tf32(__int2float_rn(w - zS) * scS);
                }
            }
            __syncthreads();
        }
    }

    // ---- epilogue: add bias, store fp32 ------------------------------------
#pragma unroll
    for (int nt = 0; nt < 8; ++nt) {
        const int c  = n0 + warp_n + nt * 8 + qcol * 2;
        const float b0 = bias[c];
        const float b1 = bias[c + 1];
#pragma unroll
        for (int mt = 0; mt < 2; ++mt) {
            const int r = m0 + warp_m + mt * 16 + qrow;
            float2 v0 = make_float2(acc[mt][nt][0] + b0, acc[mt][nt][1] + b1);
            float2 v1 = make_float2(acc[mt][nt][2] + b0, acc[mt][nt][3] + b1);
            *reinterpret_cast<float2*>(out + (long)r * kOutF + c)       = v0;
            *reinterpret_cast<float2*>(out + (long)(r + 8) * kOutF + c) = v1;
        }
    }
}

extern "C" void kernel_launch(void* const* d_in, const int* in_sizes, int n_in,
                              void* d_out, int out_size)
{
    (void)in_sizes; (void)n_in; (void)out_size;
    const float* x       = (const float*)d_in[0];
    const float* scales  = (const float*)d_in[1];
    const float* bias    = (const float*)d_in[2];
    const int*   qweight = (const int*)d_in[3];
    const int*   qzeros  = (const int*)d_in[4];
    float*       out     = (float*)d_out;

    cudaFuncSetAttribute(qlinear_tf32_kernel,
                         cudaFuncAttributeMaxDynamicSharedMemorySize, SMEM_BYTES);

    dim3 grid(kOutF / BN, kM / BM);  // (86, 64)
    qlinear_tf32_kernel<<<grid, 256, SMEM_BYTES>>>(x, scales, bias, qweight, qzeros, out);
}

// round 5
// speedup vs baseline: 3.3559x; 3.3559x over previous
#include <cuda_runtime.h>
#include <cuda_fp16.h>
#include <cstdint>

// ---------------------------------------------------------------------------
// QuantLinear, fp16 mma.sync path (base sm_103 target — tcgen05 unavailable).
//   out[8192,11008] = x[8192,4096] @ dequant(W)[4096,11008] + bias
// Pre-pass: x fp32 -> fp16 scratch, k-permuted within 8-groups to match the
// nibble-pair dequant order [v0,v4,v1,v5,v2,v6,v3,v7].
// Main: 128x128x64 CTA tile, 4 warps (64x64 warp tile), m16n8k16 fp16 MMA
// with fp32 accum, ldmatrix fragments, cp.async A loads, double-buffered.
// ---------------------------------------------------------------------------

namespace {
constexpr int kInF  = 4096;
constexpr int kOutF = 11008;
constexpr int kM    = 8192;

constexpr int BM = 128;
constexpr int BN = 128;
constexpr int BK = 64;
constexpr int NT = kInF / BK;        // 64 k-tiles

constexpr int RSTR  = 144;           // smem row stride in bytes (128B data + 16 pad)
constexpr int STAGE = 128 * RSTR;    // 18432 B per tile stage (A or B)
constexpr int S_A   = 0;             // A stages at 0, STAGE
constexpr int S_B   = 2 * STAGE;     // B stages at 2*STAGE, 3*STAGE
constexpr int SMEM_TOTAL = 4 * STAGE;  // 73728 B
}  // namespace

// 67 MB fp16 scratch for converted x (static __device__: no runtime alloc)
__device__ __align__(128) __half g_x16[(size_t)kM * kInF];

// ---------------------------------------------------------------------------
__device__ __forceinline__ uint32_t smem_u32(const void* p) {
    uint32_t a;
    asm("{ .reg .u64 t; cvta.to.shared.u64 t, %1; cvt.u32.u64 %0, t; }"
        : "=r"(a) : "l"(p));
    return a;
}

#define LDSM_X4(r0, r1, r2, r3, addr)                                          \
    asm volatile("ldmatrix.sync.aligned.m8n8.x4.shared.b16 {%0,%1,%2,%3}, [%4];" \
                 : "=r"(r0), "=r"(r1), "=r"(r2), "=r"(r3) : "r"(addr))

#define MMA16816(d, a, b0, b1)                                                \
    asm volatile(                                                             \
        "mma.sync.aligned.m16n8k16.row.col.f32.f16.f16.f32 "                  \
        "{%0,%1,%2,%3}, {%4,%5,%6,%7}, {%8,%9}, {%0,%1,%2,%3};"               \
        : "+f"((d)[0]), "+f"((d)[1]), "+f"((d)[2]), "+f"((d)[3])              \
        : "r"((a)[0]), "r"((a)[1]), "r"((a)[2]), "r"((a)[3]),                 \
          "r"(b0), "r"(b1))

#define CP_ASYNC16(dst, src)                                                  \
    asm volatile("cp.async.cg.shared.global [%0], [%1], 16;"                  \
                 :: "r"(dst), "l"(src))
#define CP_COMMIT() asm volatile("cp.async.commit_group;")
#define CP_WAIT0()  asm volatile("cp.async.wait_group 0;")

// ---------------------------------------------------------------------------
// Pre-pass: x fp32 -> fp16, permuted within each 8-k group to
// [v0,v4,v1,v5,v2,v6,v3,v7] (matches nibble-pair dequant output order).
// ---------------------------------------------------------------------------
__global__ void __launch_bounds__(256)
convert_x_kernel(const float* __restrict__ x) {
    size_t i = (size_t)blockIdx.x * blockDim.x + threadIdx.x;  // one per 8 floats
    constexpr size_t TOT = (size_t)kM * kInF / 8;
    if (i >= TOT) return;
    const float4* s = reinterpret_cast<const float4*>(x) + i * 2;
    float4 a = s[0], b = s[1];
    __half2 h0 = __floats2half2_rn(a.x, b.x);   // (v0, v4)
    __half2 h1 = __floats2half2_rn(a.y, b.y);   // (v1, v5)
    __half2 h2 = __floats2half2_rn(a.z, b.z);   // (v2, v6)
    __half2 h3 = __floats2half2_rn(a.w, b.w);   // (v3, v7)
    uint4 o;
    o.x = *reinterpret_cast<uint32_t*>(&h0);
    o.y = *reinterpret_cast<uint32_t*>(&h1);
    o.z = *reinterpret_cast<uint32_t*>(&h2);
    o.w = *reinterpret_cast<uint32_t*>(&h3);
    reinterpret_cast<uint4*>(g_x16)[i] = o;
}

// ---------------------------------------------------------------------------
// Main GEMM kernel
// ---------------------------------------------------------------------------
__global__ void __launch_bounds__(128, 2)
qlinear_hmma_kernel(const float* __restrict__ scales,
                    const float* __restrict__ bias,
                    const int*   __restrict__ qweight,
                    const int*   __restrict__ qzeros,
                    float*       __restrict__ out)
{
    extern __shared__ char smem[];
    const uint32_t sb = smem_u32(smem);
    const int tid  = threadIdx.x;
    const int lane = tid & 31;
    const int wid  = tid >> 5;               // 0..3
    const int warp_m = (wid & 1) * 64;
    const int warp_n = (wid >> 1) * 64;
    const int m0 = blockIdx.y * BM;
    const int n0 = blockIdx.x * BN;
    const int n  = n0 + tid;                 // this thread's B column

    // -------- A tile cp.async issue (tile t -> stage s) --------------------
    auto issue_a = [&](int t, int s) {
#pragma unroll
        for (int j = 0; j < 8; ++j) {
            const int idx = j * 128 + tid;   // 1024 16B chunks
            const int row = idx >> 3;
            const int col = idx & 7;
            const uint32_t dst = sb + S_A + s * STAGE + row * RSTR + col * 16;
            const __half* src = g_x16 + (size_t)(m0 + row) * kInF + t * BK + col * 8;
            CP_ASYNC16(dst, src);
        }
        CP_COMMIT();
    };

    // -------- qweight/scale/zero register staging --------------------------
    uint32_t qw[8];
    float    sc;
    int      z;
    auto ldg_qw = [&](int t) {
        const int* qp = qweight + (size_t)(t * 8) * kOutF + n;
#pragma unroll
        for (int i = 0; i < 8; ++i) qw[i] = (uint32_t)qp[(size_t)i * kOutF];
        const int g = t >> 1;                // 128-k group
        sc = scales[(size_t)g * kOutF + n];
        z  = (qzeros[(size_t)g * (kOutF / 8) + (n >> 3)] >> ((n & 7) * 4)) & 15;
    };

    // -------- B dequant -> smem stage --------------------------------------
    auto sts_b = [&](int s) {
        const uint32_t zbits = (0x6400u | (uint32_t)z) * 0x00010001u;
        const __half2 hz = *reinterpret_cast<const __half2*>(&zbits);
        const __half2 hs = __float2half2_rn(sc);
        char* bp = smem + S_B + s * STAGE + tid * RSTR;
#pragma unroll
        for (int i = 0; i < 8; ++i) {
            const uint32_t q = qw[i];
            uint32_t u0 = (q & 0x000F000Fu)         | 0x64006400u;
            uint32_t u1 = ((q >> 4) & 0x000F000Fu)  | 0x64006400u;
            uint32_t u2 = ((q >> 8) & 0x000F000Fu)  | 0x64006400u;
            uint32_t u3 = ((q >> 12) & 0x000F000Fu) | 0x64006400u;
            __half2 v0 = __hmul2(__hsub2(*reinterpret_cast<__half2*>(&u0), hz), hs);
            __half2 v1 = __hmul2(__hsub2(*reinterpret_cast<__half2*>(&u1), hz), hs);
            __half2 v2 = __hmul2(__hsub2(*reinterpret_cast<__half2*>(&u2), hz), hs);
            __half2 v3 = __hmul2(__hsub2(*reinterpret_cast<__half2*>(&u3), hz), hs);
            uint4 pk;
            pk.x = *reinterpret_cast<uint32_t*>(&v0);
            pk.y = *reinterpret_cast<uint32_t*>(&v1);
            pk.z = *reinterpret_cast<uint32_t*>(&v2);
            pk.w = *reinterpret_cast<uint32_t*>(&v3);
            *reinterpret_cast<uint4*>(bp + i * 16) = pk;
        }
    };

    // -------- accumulators --------------------------------------------------
    float acc[4][8][4];
#pragma unroll
    for (int mt = 0; mt < 4; ++mt)
#pragma unroll
        for (int nt = 0; nt < 8; ++nt)
#pragma unroll
            for (int r = 0; r < 4; ++r) acc[mt][nt][r] = 0.f;

    // lane-dependent ldmatrix base offsets
    const uint32_t a_lane = (warp_m + (lane & 15)) * RSTR + (lane >> 4) * 16;
    const uint32_t b_lane = (warp_n + (lane & 7) + ((lane >> 4) << 3)) * RSTR
                          + ((lane >> 3) & 1) * 16;

    auto compute_tile = [&](int s) {
        const uint32_t abase = sb + S_A + s * STAGE + a_lane;
        const uint32_t bbase = sb + S_B + s * STAGE + b_lane;
#pragma unroll
        for (int k16 = 0; k16 < 4; ++k16) {
            uint32_t af[4][4];
#pragma unroll
            for (int mt = 0; mt < 4; ++mt)
                LDSM_X4(af[mt][0], af[mt][1], af[mt][2], af[mt][3],
                        abase + mt * 16 * RSTR + k16 * 32);
            uint32_t bf[4][4];
#pragma unroll
            for (int nt2 = 0; nt2 < 4; ++nt2)
                LDSM_X4(bf[nt2][0], bf[nt2][1], bf[nt2][2], bf[nt2][3],
                        bbase + nt2 * 16 * RSTR + k16 * 32);
#pragma unroll
            for (int mt = 0; mt < 4; ++mt)
#pragma unroll
                for (int nt = 0; nt < 8; ++nt) {
                    const int h = (nt & 1) * 2;
                    MMA16816(acc[mt][nt], af[mt], bf[nt >> 1][h], bf[nt >> 1][h + 1]);
                }
        }
    };

    // -------- prologue ------------------------------------------------------
    issue_a(0, 0);
    ldg_qw(0);
    sts_b(0);
    CP_WAIT0();
    __syncthreads();

    // -------- main loop -----------------------------------------------------
    for (int t = 0; t < NT; ++t) {
        const int s = t & 1;
        const bool more = (t + 1 < NT);
        if (more) {
            issue_a(t + 1, s ^ 1);
            ldg_qw(t + 1);
        }
        compute_tile(s);
        if (more) {
            sts_b(s ^ 1);
            CP_WAIT0();
            __syncthreads();
        }
    }

    // -------- epilogue: +bias, fp32 stores ---------------------------------
    const int g  = lane >> 2;
    const int tg = lane & 3;
#pragma unroll
    for (int nt = 0; nt < 8; ++nt) {
        const int c = n0 + warp_n + nt * 8 + tg * 2;
        const float2 bv = *reinterpret_cast<const float2*>(bias + c);
#pragma unroll
        for (int mt = 0; mt < 4; ++mt) {
            const int r0 = m0 + warp_m + mt * 16 + g;
            float2 v0 = make_float2(acc[mt][nt][0] + bv.x, acc[mt][nt][1] + bv.y);
            float2 v1 = make_float2(acc[mt][nt][2] + bv.x, acc[mt][nt][3] + bv.y);
            *reinterpret_cast<float2*>(out + (size_t)r0 * kOutF + c)       = v0;
            *reinterpret_cast<float2*>(out + (size_t)(r0 + 8) * kOutF + c) = v1;
        }
    }
}

// ---------------------------------------------------------------------------
extern "C" void kernel_launch(void* const* d_in, const int* in_sizes, int n_in,
                              void* d_out, int out_size)
{
    (void)in_sizes; (void)n_in; (void)out_size;
    const float* x       = (const float*)d_in[0];
    const float* scales  = (const float*)d_in[1];
    const float* bias    = (const float*)d_in[2];
    const int*   qweight = (const int*)d_in[3];
    const int*   qzeros  = (const int*)d_in[4];
    float*       out     = (float*)d_out;

    const size_t tot8 = (size_t)kM * kInF / 8;
    convert_x_kernel<<<(unsigned)((tot8 + 255) / 256), 256>>>(x);

    cudaFuncSetAttribute(qlinear_hmma_kernel,
                         cudaFuncAttributeMaxDynamicSharedMemorySize, SMEM_TOTAL);
    dim3 grid(kOutF / BN, kM / BM);  // (86, 64)
    qlinear_hmma_kernel<<<grid, 128, SMEM_TOTAL>>>(scales, bias, qweight, qzeros, out);
}